// round 17
// baseline (speedup 1.0000x reference)
#include <cuda_runtime.h>
#include <stdint.h>

#define BATCH 64
#define TT    512
#define HH    768
#define KK    4
#define ROWS  (BATCH*TT)   // 32768
#define NCHUNK 32
#define CL     16          // backtrack chunk length (NCHUNK*CL = 512)

typedef unsigned long long u64;

// Scratch (no cudaMalloc allowed). [t][b]-major for coalesced lane access.
__device__ float4   g_emis[(TT+8)*BATCH];   // [t*64+b], +8 rows pad for prefetch overrun
__device__ float4   g_scores[TT*BATCH];     // [t*64+b] viterbi scores
__device__ unsigned g_map32[TT*BATCH];      // [s*64+b] byte-form backpointer maps
__device__ unsigned g_cmap[NCHUNK*BATCH];   // [c*64+b] chunk-composed map
__device__ int      g_btag[NCHUNK*BATCH];   // [c*64+b] incoming tag for chunk replay
__device__ int      g_best[BATCH];
// producer->consumer flags: one array per consumer block; zero-initialized at
// load, and each consumer resets every flag it consumes => zero again at exit
// (deterministic across graph replays, no static host state).
__device__ unsigned g_cntA[TT];
__device__ unsigned g_cntB[TT];

// pack byte-form map (bytes 0..3, values 0..3) into a PRMT nibble selector
__device__ __forceinline__ unsigned nibsel(unsigned x) {
    unsigned y = x | (x >> 4);
    unsigned t = y & 0x00FF00FFu;
    return (t | (t >> 8)) & 0xFFFFu;
}

// ---- Blackwell packed f32x2 helpers (exact elementwise IEEE fp32) ----------
__device__ __forceinline__ u64 f2pack(float lo, float hi) {
    u64 r; asm("mov.b64 %0, {%1, %2};" : "=l"(r) : "f"(lo), "f"(hi)); return r;
}
__device__ __forceinline__ void f2unpack(float& lo, float& hi, u64 v) {
    asm("mov.b64 {%0, %1}, %2;" : "=f"(lo), "=f"(hi) : "l"(v));
}
__device__ __forceinline__ u64 f2add(u64 a, u64 b) {
    u64 r; asm("add.rn.f32x2 %0, %1, %2;" : "=l"(r) : "l"(a), "l"(b)); return r;
}

// acquire-load spin until flag == 8, then reset (lane 0)
__device__ __forceinline__ void wait_and_clear(unsigned* cnt, int t, int lane) {
    unsigned v;
    do {
        asm volatile("ld.acquire.gpu.global.u32 %0, [%1];"
                     : "=r"(v) : "l"(cnt + t) : "memory");
    } while (v < 8u);
    __syncwarp();
    if (lane == 0)
        asm volatile("st.global.relaxed.gpu.u32 [%0], %1;"
                     :: "l"(cnt + t), "r"(0u) : "memory");
}

// ---------------------------------------------------------------------------
// K_FUSED: blocks 0,1 = Viterbi forward scan (32 lanes each, wave-1 resident);
// blocks 2..4097 = emissions, t-major so completion order matches consumption.
// ---------------------------------------------------------------------------
__global__ __launch_bounds__(256) void k_fused(
    const float* __restrict__ sent,    // [B,T,H]
    const float* __restrict__ W,       // [K,H]
    const float* __restrict__ bias,    // [K]
    const float* __restrict__ startT,
    const float* __restrict__ endT,
    const float* __restrict__ trans)   // [K,K], trans[i*4+j]
{
    if (blockIdx.x >= 2) {
        // ================= producer: emissions (t-major rows) ===============
        __shared__ float4 sW[KK][HH/4];   // 12 KB
        __shared__ float  sb[KK];
        int tid = threadIdx.x;

        const float4* W4 = (const float4*)W;
        for (int i = tid; i < KK*(HH/4); i += blockDim.x)
            sW[i/(HH/4)][i%(HH/4)] = W4[i];
        if (tid < KK) sb[tid] = bias[tid];
        __syncthreads();

        int eb   = blockIdx.x - 2;            // 0..4095
        int warp = tid >> 5, lane = tid & 31;
        int row  = eb*8 + warp;               // row = t*64 + b  (t-major!)
        int t    = row >> 6;
        int b    = row & 63;

        const float4* x = (const float4*)(sent + ((size_t)b*TT + t) * HH);
        float a0 = 0.f, a1 = 0.f, a2 = 0.f, a3 = 0.f;
        #pragma unroll
        for (int i = 0; i < HH/128; i++) {    // 6 iterations
            int idx = i*32 + lane;
            float4 v  = x[idx];
            float4 w0 = sW[0][idx];
            float4 w1 = sW[1][idx];
            float4 w2 = sW[2][idx];
            float4 w3 = sW[3][idx];
            a0 += v.x*w0.x + v.y*w0.y + v.z*w0.z + v.w*w0.w;
            a1 += v.x*w1.x + v.y*w1.y + v.z*w1.z + v.w*w1.w;
            a2 += v.x*w2.x + v.y*w2.y + v.z*w2.z + v.w*w2.w;
            a3 += v.x*w3.x + v.y*w3.y + v.z*w3.z + v.w*w3.w;
        }
        #pragma unroll
        for (int d = 16; d; d >>= 1) {
            a0 += __shfl_xor_sync(0xffffffffu, a0, d);
            a1 += __shfl_xor_sync(0xffffffffu, a1, d);
            a2 += __shfl_xor_sync(0xffffffffu, a2, d);
            a3 += __shfl_xor_sync(0xffffffffu, a3, d);
        }
        if (lane == 0) {
            g_emis[t*BATCH + b] = make_float4(a0 + sb[0], a1 + sb[1],
                                              a2 + sb[2], a3 + sb[3]);
            __threadfence();                  // each writer fences its store
        }
        __syncthreads();                      // all 8 rows (same t) done+fenced
        if (tid == 0) {
            atomicAdd(&g_cntA[t], 1u);
            atomicAdd(&g_cntB[t], 1u);
        }
        return;
    }

    // ================= consumer: forward scan (blocks 0,1) ==================
    int lane = threadIdx.x & 31;
    if (threadIdx.x >= 32) return;
    int b = blockIdx.x * 32 + lane;           // 0..63
    unsigned* cnt = (blockIdx.x == 0) ? g_cntA : g_cntB;

    // packed transition columns: C01[j]=(T[0][j],T[1][j]), C23[j]=(T[2][j],T[3][j])
    u64 C01[4], C23[4];
    #pragma unroll
    for (int j = 0; j < 4; j++) {
        C01[j] = f2pack(__ldg(trans + 0*4 + j), __ldg(trans + 1*4 + j));
        C23[j] = f2pack(__ldg(trans + 2*4 + j), __ldg(trans + 3*4 + j));
    }

    // wait for t = 0..8 before the initial loads
    #pragma unroll
    for (int t0 = 0; t0 <= 8; t0++) wait_and_clear(cnt, t0, lane);

    float4 e0 = g_emis[0*BATCH + b];
    float s0 = __ldg(startT+0) + e0.x;
    float s1 = __ldg(startT+1) + e0.y;
    float s2 = __ldg(startT+2) + e0.z;
    float s3 = __ldg(startT+3) + e0.w;
    g_scores[0*BATCH + b] = make_float4(s0, s1, s2, s3);

    u64 P01 = f2pack(s0, s1);
    u64 P23 = f2pack(s2, s3);

    float4 buf[8];
    #pragma unroll
    for (int j = 0; j < 8; j++) buf[j] = g_emis[(1 + j)*BATCH + b];

    // main: t = 1..504; flag (t+8) waited exactly once, then prefetch
    for (int base = 1; base <= 497; base += 8) {
        #pragma unroll
        for (int j = 0; j < 8; j++) {
            int t = base + j;
            float4 e = buf[j];
            int tp = t + 8;
            if (tp <= 511) wait_and_clear(cnt, tp, lane);
            buf[j] = g_emis[tp*BATCH + b];    // row 512 is padding (unused data)

            float m0, m1, m2, m3;
            {
                u64 a = f2add(P01, C01[0]); u64 c = f2add(P23, C23[0]);
                float x0,x1,y0,y1; f2unpack(x0,x1,a); f2unpack(y0,y1,c);
                m0 = fmaxf(fmaxf(x0,x1), fmaxf(y0,y1));
            }
            {
                u64 a = f2add(P01, C01[1]); u64 c = f2add(P23, C23[1]);
                float x0,x1,y0,y1; f2unpack(x0,x1,a); f2unpack(y0,y1,c);
                m1 = fmaxf(fmaxf(x0,x1), fmaxf(y0,y1));
            }
            {
                u64 a = f2add(P01, C01[2]); u64 c = f2add(P23, C23[2]);
                float x0,x1,y0,y1; f2unpack(x0,x1,a); f2unpack(y0,y1,c);
                m2 = fmaxf(fmaxf(x0,x1), fmaxf(y0,y1));
            }
            {
                u64 a = f2add(P01, C01[3]); u64 c = f2add(P23, C23[3]);
                float x0,x1,y0,y1; f2unpack(x0,x1,a); f2unpack(y0,y1,c);
                m3 = fmaxf(fmaxf(x0,x1), fmaxf(y0,y1));
            }
            P01 = f2add(f2pack(m0, m1), f2pack(e.x, e.y));
            P23 = f2add(f2pack(m2, m3), f2pack(e.z, e.w));

            ulonglong2 st; st.x = P01; st.y = P23;
            *(ulonglong2*)&g_scores[t*BATCH + b] = st;
        }
    }

    // tail: t = 505..511 (buf holds em[505..511]; their flags already cleared)
    #pragma unroll
    for (int j = 0; j < 7; j++) {
        int t = 505 + j;
        float4 e = buf[j];
        float m0, m1, m2, m3;
        {
            u64 a = f2add(P01, C01[0]); u64 c = f2add(P23, C23[0]);
            float x0,x1,y0,y1; f2unpack(x0,x1,a); f2unpack(y0,y1,c);
            m0 = fmaxf(fmaxf(x0,x1), fmaxf(y0,y1));
        }
        {
            u64 a = f2add(P01, C01[1]); u64 c = f2add(P23, C23[1]);
            float x0,x1,y0,y1; f2unpack(x0,x1,a); f2unpack(y0,y1,c);
            m1 = fmaxf(fmaxf(x0,x1), fmaxf(y0,y1));
        }
        {
            u64 a = f2add(P01, C01[2]); u64 c = f2add(P23, C23[2]);
            float x0,x1,y0,y1; f2unpack(x0,x1,a); f2unpack(y0,y1,c);
            m2 = fmaxf(fmaxf(x0,x1), fmaxf(y0,y1));
        }
        {
            u64 a = f2add(P01, C01[3]); u64 c = f2add(P23, C23[3]);
            float x0,x1,y0,y1; f2unpack(x0,x1,a); f2unpack(y0,y1,c);
            m3 = fmaxf(fmaxf(x0,x1), fmaxf(y0,y1));
        }
        P01 = f2add(f2pack(m0, m1), f2pack(e.x, e.y));
        P23 = f2add(f2pack(m2, m3), f2pack(e.z, e.w));

        ulonglong2 st; st.x = P01; st.y = P23;
        *(ulonglong2*)&g_scores[t*BATCH + b] = st;
    }

    // final: add end transitions, argmax over 4 (strict >, first index wins)
    float s0f, s1f, s2f, s3f;
    f2unpack(s0f, s1f, P01);
    f2unpack(s2f, s3f, P23);
    float f0 = s0f + __ldg(endT+0);
    float f1 = s1f + __ldg(endT+1);
    float f2 = s2f + __ldg(endT+2);
    float f3 = s3f + __ldg(endT+3);
    int best = 0; float m = f0;
    if (f1 > m) { m = f1; best = 1; }
    if (f2 > m) { m = f2; best = 2; }
    if (f3 > m) { m = f3; best = 3; }
    g_best[b] = best;
}

// ---------------------------------------------------------------------------
// K3: per (chunk c, batch b): per-step backpointer maps
//   f_s[j] = argmax_i ( scores[s][i] + trans[i][j] ), first-index wins,
// stored + chunk-composed map F_c (exact integer composition via PRMT).
// ---------------------------------------------------------------------------
__global__ __launch_bounds__(64) void k_chunk(const float* __restrict__ trans)
{
    int b = threadIdx.x;
    int c = blockIdx.x;
    int sbase = c * CL;
    int ns = (c == NCHUNK-1) ? (CL-1) : CL;   // chunk 31 covers s=496..510

    float tr[16];
    #pragma unroll
    for (int i = 0; i < 16; i++) tr[i] = __ldg(trans + i);

    unsigned m[CL];
    #pragma unroll
    for (int k = 0; k < CL; k++) {
        if (k < ns) {
            float4 sc = g_scores[(sbase + k)*BATCH + b];
            unsigned hh = 0;
            #pragma unroll
            for (int j = 0; j < 4; j++) {
                float c0 = sc.x + tr[0*4+j];
                float c1 = sc.y + tr[1*4+j];
                float c2 = sc.z + tr[2*4+j];
                float c3 = sc.w + tr[3*4+j];
                int bp = 0; float mm = c0;
                if (c1 > mm) { mm = c1; bp = 1; }
                if (c2 > mm) { mm = c2; bp = 2; }
                if (c3 > mm) { mm = c3; bp = 3; }
                hh |= (unsigned)bp << (8*j);
            }
            m[k] = hh;
            g_map32[(sbase + k)*BATCH + b] = hh;
        }
    }

    unsigned F = m[ns-1];
    #pragma unroll
    for (int k = CL-2; k >= 0; k--)
        if (k <= ns-2)
            F = __byte_perm(m[k], 0, nibsel(F));
    g_cmap[c*BATCH + b] = F;
}

// ---------------------------------------------------------------------------
// K3b: suffix walk over chunk maps -> incoming tag per chunk; writes out[511].
// ---------------------------------------------------------------------------
__global__ __launch_bounds__(64) void k_btag(float* __restrict__ out)
{
    int b = threadIdx.x;
    unsigned Fs[NCHUNK];
    #pragma unroll
    for (int c = 0; c < NCHUNK; c++) Fs[c] = g_cmap[c*BATCH + b];

    int t = g_best[b];
    out[b*TT + (TT-1)] = (float)t;
    #pragma unroll
    for (int c = NCHUNK-1; c >= 0; c--) {
        g_btag[c*BATCH + b] = t;
        t = __byte_perm(Fs[c], 0, t) & 3;
    }
}

// ---------------------------------------------------------------------------
// K4: parallel chunk replay. thread (c,b): 16 PRMT steps, coalesced map loads.
// ---------------------------------------------------------------------------
__global__ __launch_bounds__(64) void k_replay(float* __restrict__ out)
{
    int b = threadIdx.x;
    int c = blockIdx.x;
    int sbase = c * CL;
    int ns = (c == NCHUNK-1) ? (CL-1) : CL;

    unsigned m[CL];
    #pragma unroll
    for (int k = 0; k < CL; k++)
        if (k < ns) m[k] = g_map32[(sbase + k)*BATCH + b];

    int tag = g_btag[c*BATCH + b];
    #pragma unroll
    for (int k = CL-1; k >= 0; k--) {
        if (k < ns) {
            tag = __byte_perm(m[k], 0, tag) & 3;
            out[b*TT + sbase + k] = (float)tag;
        }
    }
}

// ---------------------------------------------------------------------------
// Bind inputs BY ELEMENT COUNT (robust to input-order permutation).
// The three 4-element vectors keep their relative order: b, start, end.
// __output__ dtype is float32 (established R7).
// ---------------------------------------------------------------------------
extern "C" void kernel_launch(void* const* d_in, const int* in_sizes, int n_in,
                              void* d_out, int out_size)
{
    const float* sent   = 0;
    const float* W      = 0;
    const float* bias   = 0;
    const float* startT = 0;
    const float* endT   = 0;
    const float* trans  = 0;

    int n4 = 0;
    for (int i = 0; i < n_in; i++) {
        int sz = in_sizes[i];
        const float* p = (const float*)d_in[i];
        if      (sz == BATCH*TT*HH) sent  = p;
        else if (sz == KK*HH)       W     = p;
        else if (sz == KK*KK)       trans = p;
        else if (sz == KK) {
            if      (n4 == 0) bias   = p;
            else if (n4 == 1) startT = p;
            else              endT   = p;
            n4++;
        }
    }
    float* out = (float*)d_out;                   // [64,512] float32

    k_fused<<<4098, 256>>>(sent, W, bias, startT, endT, trans);
    k_chunk<<<NCHUNK, 64>>>(trans);
    k_btag<<<1, 64>>>(out);
    k_replay<<<NCHUNK, 64>>>(out);
}